// round 8
// baseline (speedup 1.0000x reference)
#include <cuda_runtime.h>
#include <cuda_bf16.h>
#include <cstdint>

#define BATCH 512
#define GS 2048
#define PARAM 64
#define OGS 1024
#define KDIM 128
#define NDIM 64
#define TILE_ROWS 128

#define APITCH 136          // halves per A row (272B: ldmatrix conflict-free)
#define OFF_AH 0
#define OFF_AL (OFF_AH + TILE_ROWS * APITCH * 2)          // 34816
#define SMEM_BYTES (OFF_AL + TILE_ROWS * APITCH * 2)      // 69632

__device__ unsigned int g_order[BATCH * GS];
// B mma-fragments: [ng(2)][kc(8)][group g(4)][lane(32)] uint4.
__device__ __align__(16) uint4 g_Bfrag[2 * 8 * 4 * 32];
__device__ int g_flag[BATCH];
__device__ int g_bflag;
__device__ unsigned int g_done;

__device__ __forceinline__ uint32_t smem_u32(const void* p) {
    uint32_t a;
    asm("{ .reg .u64 t; cvta.to.shared.u64 t, %1; cvt.u32.u64 %0, t; }" : "=r"(a) : "l"(p));
    return a;
}
__device__ __forceinline__ int ld_acquire(const int* p) {
    int v;
    asm volatile("ld.acquire.gpu.global.b32 %0, [%1];" : "=r"(v) : "l"(p) : "memory");
    return v;
}
__device__ __forceinline__ void st_release(int* p, int v) {
    asm volatile("st.release.gpu.global.b32 [%0], %1;" :: "l"(p), "r"(v) : "memory");
}

#define LDM4(r, addr) \
    asm volatile("ldmatrix.sync.aligned.m8n8.x4.shared.b16 {%0,%1,%2,%3}, [%4];" \
        : "=r"((r)[0]), "=r"((r)[1]), "=r"((r)[2]), "=r"((r)[3]) : "r"(addr))

#define MMA(d, a, b0v, b1v) \
    asm volatile("mma.sync.aligned.m16n8k16.row.col.f32.bf16.bf16.f32 " \
        "{%0,%1,%2,%3},{%4,%5,%6,%7},{%8,%9},{%0,%1,%2,%3};" \
        : "+f"((d)[0]), "+f"((d)[1]), "+f"((d)[2]), "+f"((d)[3]) \
        : "r"((a)[0]), "r"((a)[1]), "r"((a)[2]), "r"((a)[3]), "r"(b0v), "r"(b1v))

__device__ __forceinline__ void bf16_split(float v, unsigned short& h, unsigned short& l) {
    __nv_bfloat16 bh = __float2bfloat16_rn(v);
    float r = v - __bfloat162float(bh);
    __nv_bfloat16 bl = __float2bfloat16_rn(r);
    h = *(unsigned short*)&bh;
    l = *(unsigned short*)&bl;
}

__device__ __forceinline__ void ce(unsigned long long& a, unsigned long long& b, bool up) {
    if ((a > b) == up) { unsigned long long t = a; a = b; b = t; }
}
__device__ __forceinline__ void merge8(unsigned long long* k, bool up) {
    ce(k[0], k[4], up); ce(k[1], k[5], up); ce(k[2], k[6], up); ce(k[3], k[7], up);
    ce(k[0], k[2], up); ce(k[1], k[3], up); ce(k[4], k[6], up); ce(k[5], k[7], up);
    ce(k[0], k[1], up); ce(k[2], k[3], up); ce(k[4], k[5], up); ce(k[6], k[7], up);
}

// ---------------------------------------------------------------------------
// Fused kernel. grid = (8, 512), block = 256, 3 CTAs/SM.
//  - bid == 0  : precompute B mma-fragment table (2 halves), release g_bflag
//  - bid < 512 : bitonic-sort batch `bid` (256 thr x 8 keys), release flag
//  - all       : acquire flag[y], gather tile, acquire bflag, M32N32 GEMM
// ---------------------------------------------------------------------------
__global__ __launch_bounds__(256, 3) void fused_kernel(const float* __restrict__ x,
                                                       const float* __restrict__ trafo,
                                                       float* __restrict__ out) {
    extern __shared__ char smem[];
    __shared__ unsigned s_last;

    const int y = blockIdx.y;
    const int bid = blockIdx.x + (y << 3);
    const int tileRow = blockIdx.x * TILE_ROWS;
    const int t = threadIdx.x;
    const int wid = t >> 5;
    const int lid = t & 31;

    // ---- B-fragment table (bid 0; 512 items, 2 per thread) ----
    if (bid == 0) {
        #pragma unroll
        for (int half = 0; half < 2; half++) {
            int it = t + 256 * half;
            int ng = it >> 8;
            int kc = (it >> 5) & 7;
            int lane = it & 31;
            int n_base = ng * 32 + (lane >> 2);
            int k_base = kc * 16 + 2 * (lane & 3);
            uint32_t rh[8], rl[8];
            #pragma unroll
            for (int nt = 0; nt < 4; nt++)
                #pragma unroll
                for (int r = 0; r < 2; r++) {
                    int n = n_base + 8 * nt;
                    int k = k_base + 8 * r;
                    unsigned short h0, l0, h1, l1;
                    bf16_split(trafo[k * NDIM + n], h0, l0);
                    bf16_split(trafo[(k + 1) * NDIM + n], h1, l1);
                    rh[2 * nt + r] = (uint32_t)h0 | ((uint32_t)h1 << 16);
                    rl[2 * nt + r] = (uint32_t)l0 | ((uint32_t)l1 << 16);
                }
            uint4* dst = g_Bfrag + (ng * 8 + kc) * 128 + lane;
            dst[0]  = make_uint4(rh[0], rh[1], rh[2], rh[3]);
            dst[32] = make_uint4(rh[4], rh[5], rh[6], rh[7]);
            dst[64] = make_uint4(rl[0], rl[1], rl[2], rl[3]);
            dst[96] = make_uint4(rl[4], rl[5], rl[6], rl[7]);
        }
        __syncthreads();
        __threadfence();
        if (t == 0) st_release(&g_bflag, 1);
    }

    // ---- Sort batch `bid` (bid < 512): 256 threads x 8 keys ----
    if (bid < BATCH) {
        unsigned long long* keys = (unsigned long long*)smem;   // 16KB overlay
        const float* xb = x + (size_t)bid * GS * PARAM;

        unsigned long long key[8];
        #pragma unroll
        for (int i = 0; i < 8; i++) {
            int e = 8 * t + i;
            unsigned u = __float_as_uint(xb[(size_t)e * PARAM + (PARAM - 1)]);
            unsigned m = (u & 0x80000000u) ? ~u : (u | 0x80000000u);
            key[i] = ((unsigned long long)(~m) << 32) | (unsigned)e;
        }

        ce(key[0], key[1], true);  ce(key[2], key[3], false);
        ce(key[4], key[5], true);  ce(key[6], key[7], false);
        ce(key[0], key[2], true);  ce(key[1], key[3], true);
        ce(key[0], key[1], true);  ce(key[2], key[3], true);
        ce(key[4], key[6], false); ce(key[5], key[7], false);
        ce(key[4], key[5], false); ce(key[6], key[7], false);
        merge8(key, (t & 1) == 0);

        #pragma unroll
        for (int k = 16; k <= 256; k <<= 1) {
            bool up = ((t & (k >> 3)) == 0);
            #pragma unroll
            for (int j = k >> 1; j >= 8; j >>= 1) {
                int d = j >> 3;
                bool keepmin = (((t & d) == 0) == up);
                #pragma unroll
                for (int i = 0; i < 8; i++) {
                    unsigned long long p = __shfl_xor_sync(0xffffffffu, key[i], d);
                    key[i] = keepmin ? (key[i] < p ? key[i] : p) : (key[i] > p ? key[i] : p);
                }
            }
            merge8(key, up);
        }

        for (int k = 512; k <= GS; k <<= 1) {
            #pragma unroll
            for (int i = 0; i < 8; i++) keys[8 * t + i] = key[i];
            __syncthreads();
            for (int j = k >> 1; j >= 256; j >>= 1) {
                #pragma unroll
                for (int q0 = 0; q0 < 4; q0++) {
                    int q = t + 256 * q0;
                    int i = ((q & ~(j - 1)) << 1) | (q & (j - 1));
                    bool up2 = ((i & k) == 0);
                    unsigned long long a = keys[i];
                    unsigned long long c = keys[i | j];
                    if ((a > c) == up2) { keys[i] = c; keys[i | j] = a; }
                }
                __syncthreads();
            }
            #pragma unroll
            for (int i = 0; i < 8; i++) key[i] = keys[8 * t + i];
            bool up = ((t & (k >> 3)) == 0);
            #pragma unroll
            for (int j = 128; j >= 8; j >>= 1) {
                int d = j >> 3;
                bool keepmin = (((t & d) == 0) == up);
                #pragma unroll
                for (int i = 0; i < 8; i++) {
                    unsigned long long p = __shfl_xor_sync(0xffffffffu, key[i], d);
                    key[i] = keepmin ? (key[i] < p ? key[i] : p) : (key[i] > p ? key[i] : p);
                }
            }
            merge8(key, up);
        }

        #pragma unroll
        for (int i = 0; i < 8; i++)
            g_order[bid * GS + 8 * t + i] = (unsigned)(key[i] & 0xffffffffu);

        __syncthreads();
        __threadfence();
        if (t == 0) st_release(&g_flag[bid], 1);
    }

    // ---- Wait for this batch's order (sorter bid = y <= our bid) ----
    if (t == 0) {
        while (ld_acquire(&g_flag[y]) == 0) __nanosleep(64);
    }
    __syncthreads();

    // ---- Gather 256 x-rows -> bf16 hi/lo A tiles (idx prefetch) ----
    unsigned short* Ah = (unsigned short*)(smem + OFF_AH);
    unsigned short* Al = (unsigned short*)(smem + OFF_AL);
    {
        const float* xb = x + (size_t)y * GS * PARAM;
        const int lane16 = t & 15;
        const unsigned* ord = g_order + y * GS + 2 * tileRow;
        unsigned idx[16];
        #pragma unroll
        for (int pass = 0; pass < 16; pass++)
            idx[pass] = ord[pass * 16 + (t >> 4)];
        #pragma unroll
        for (int pass = 0; pass < 16; pass++) {
            int s = pass * 16 + (t >> 4);
            float4 v = ((const float4*)(xb + (size_t)idx[pass] * PARAM))[lane16];
            int r = s >> 1;
            int koff = (s & 1) * PARAM + lane16 * 4;
            unsigned short h[4], l[4];
            bf16_split(v.x, h[0], l[0]);
            bf16_split(v.y, h[1], l[1]);
            bf16_split(v.z, h[2], l[2]);
            bf16_split(v.w, h[3], l[3]);
            uint2 hp, lp;
            hp.x = (uint32_t)h[0] | ((uint32_t)h[1] << 16);
            hp.y = (uint32_t)h[2] | ((uint32_t)h[3] << 16);
            lp.x = (uint32_t)l[0] | ((uint32_t)l[1] << 16);
            lp.y = (uint32_t)l[2] | ((uint32_t)l[3] << 16);
            *(uint2*)(Ah + r * APITCH + koff) = hp;
            *(uint2*)(Al + r * APITCH + koff) = lp;
        }
    }

    if (t == 0) {
        while (ld_acquire(&g_bflag) == 0) __nanosleep(64);
    }
    __syncthreads();

    // ---- Mainloop: 8 warps, warp w -> rows (w&3)*32, cols (w>>2)*32 ----
    const int wm = (wid & 3) * 32;
    const int ng = wid >> 2;
    const uint32_t sb32 = smem_u32(smem);

    uint32_t a_addr = sb32 + OFF_AH +
        (((uint32_t)(wm + (lid & 15)) * APITCH + (uint32_t)((lid >> 4) * 8)) << 1);
    const uint32_t A_LO = OFF_AL - OFF_AH;
    const uint32_t A_MT = 16 * APITCH * 2;

    const uint4* Bf = g_Bfrag + ng * (8 * 128) + lid;

    float d[2][4][4];
    #pragma unroll
    for (int mt = 0; mt < 2; mt++)
        #pragma unroll
        for (int nt = 0; nt < 4; nt++)
            #pragma unroll
            for (int e = 0; e < 4; e++) d[mt][nt][e] = 0.f;

    #pragma unroll
    for (int kc = 0; kc < 8; kc++) {
        const uint32_t ko = kc * 32;
        uint4 f0 = __ldg(Bf + kc * 128);          // bh[0..3]
        uint4 f1 = __ldg(Bf + kc * 128 + 32);     // bh[4..7]
        uint4 f2 = __ldg(Bf + kc * 128 + 64);     // bl[0..3]
        uint4 f3 = __ldg(Bf + kc * 128 + 96);     // bl[4..7]
        uint32_t ah[2][4], al[2][4];
        LDM4(ah[0], a_addr + ko);
        LDM4(ah[1], a_addr + A_MT + ko);
        LDM4(al[0], a_addr + A_LO + ko);
        LDM4(al[1], a_addr + A_LO + A_MT + ko);

        #pragma unroll
        for (int mt = 0; mt < 2; mt++) {
            MMA(d[mt][0], ah[mt], f0.x, f0.y);
            MMA(d[mt][1], ah[mt], f0.z, f0.w);
            MMA(d[mt][2], ah[mt], f1.x, f1.y);
            MMA(d[mt][3], ah[mt], f1.z, f1.w);
            MMA(d[mt][0], ah[mt], f2.x, f2.y);
            MMA(d[mt][1], ah[mt], f2.z, f2.w);
            MMA(d[mt][2], ah[mt], f3.x, f3.y);
            MMA(d[mt][3], ah[mt], f3.z, f3.w);
            MMA(d[mt][0], al[mt], f0.x, f0.y);
            MMA(d[mt][1], al[mt], f0.z, f0.w);
            MMA(d[mt][2], al[mt], f1.x, f1.y);
            MMA(d[mt][3], al[mt], f1.z, f1.w);
        }
    }

    float* baseo = out + ((size_t)y * OGS + tileRow) * NDIM;
    const int wn = ng * 32;
    #pragma unroll
    for (int mt = 0; mt < 2; mt++)
        #pragma unroll
        for (int nt = 0; nt < 4; nt++) {
            int r = wm + 16 * mt + (lid >> 2);
            int c = wn + 8 * nt + 2 * (lid & 3);
            *(float2*)(baseo + (size_t)r * NDIM + c) =
                make_float2(d[mt][nt][0], d[mt][nt][1]);
            *(float2*)(baseo + (size_t)(r + 8) * NDIM + c) =
                make_float2(d[mt][nt][2], d[mt][nt][3]);
        }

    // ---- Flag reset by the last CTA to finish ----
    __syncthreads();
    if (t == 0) {
        unsigned done = atomicAdd(&g_done, 1u);
        s_last = (done == (unsigned)(8 * BATCH - 1)) ? 1u : 0u;
    }
    __syncthreads();
    if (s_last) {
        for (int i = t; i < BATCH; i += 256) g_flag[i] = 0;
        if (t == 0) { g_bflag = 0; g_done = 0u; }
    }
}

extern "C" void kernel_launch(void* const* d_in, const int* in_sizes, int n_in,
                              void* d_out, int out_size) {
    const float* x     = (const float*)d_in[0];
    const float* trafo = (const float*)d_in[1];
    float* out         = (float*)d_out;

    cudaFuncSetAttribute(fused_kernel, cudaFuncAttributeMaxDynamicSharedMemorySize,
                         SMEM_BYTES);
    dim3 grid(OGS / TILE_ROWS, BATCH);
    fused_kernel<<<grid, 256, SMEM_BYTES>>>(x, trafo, out);
}

// round 9
// speedup vs baseline: 1.0536x; 1.0536x over previous
#include <cuda_runtime.h>
#include <cuda_bf16.h>
#include <cstdint>

#define BATCH 512
#define GS 2048
#define PARAM 64
#define OGS 1024
#define KDIM 128
#define NDIM 64
#define TILE_ROWS 128

#define APITCH 136          // halves per A row (272B: ldmatrix conflict-free)
#define OFF_AH 0
#define OFF_AL (OFF_AH + TILE_ROWS * APITCH * 2)          // 34816
#define SMEM_BYTES (OFF_AL + TILE_ROWS * APITCH * 2)      // 69632

__device__ unsigned int g_order[BATCH * GS];
// B mma-fragments: [ng(2)][kc(8)][group g(4)][lane(32)] uint4.
__device__ __align__(16) uint4 g_Bfrag[2 * 8 * 4 * 32];
__device__ int g_flag[BATCH];
__device__ int g_bflag;
__device__ unsigned int g_done;

__device__ __forceinline__ uint32_t smem_u32(const void* p) {
    uint32_t a;
    asm("{ .reg .u64 t; cvta.to.shared.u64 t, %1; cvt.u32.u64 %0, t; }" : "=r"(a) : "l"(p));
    return a;
}
__device__ __forceinline__ int ld_acquire(const int* p) {
    int v;
    asm volatile("ld.acquire.gpu.global.b32 %0, [%1];" : "=r"(v) : "l"(p) : "memory");
    return v;
}
__device__ __forceinline__ void st_release(int* p, int v) {
    asm volatile("st.release.gpu.global.b32 [%0], %1;" :: "l"(p), "r"(v) : "memory");
}

#define LDM4(r, addr) \
    asm volatile("ldmatrix.sync.aligned.m8n8.x4.shared.b16 {%0,%1,%2,%3}, [%4];" \
        : "=r"((r)[0]), "=r"((r)[1]), "=r"((r)[2]), "=r"((r)[3]) : "r"(addr))

#define MMA(d, a, b0v, b1v) \
    asm volatile("mma.sync.aligned.m16n8k16.row.col.f32.bf16.bf16.f32 " \
        "{%0,%1,%2,%3},{%4,%5,%6,%7},{%8,%9},{%0,%1,%2,%3};" \
        : "+f"((d)[0]), "+f"((d)[1]), "+f"((d)[2]), "+f"((d)[3]) \
        : "r"((a)[0]), "r"((a)[1]), "r"((a)[2]), "r"((a)[3]), "r"(b0v), "r"(b1v))

__device__ __forceinline__ void bf16_split(float v, unsigned short& h, unsigned short& l) {
    __nv_bfloat16 bh = __float2bfloat16_rn(v);
    float r = v - __bfloat162float(bh);
    __nv_bfloat16 bl = __float2bfloat16_rn(r);
    h = *(unsigned short*)&bh;
    l = *(unsigned short*)&bl;
}

__device__ __forceinline__ void ce(unsigned long long& a, unsigned long long& b, bool up) {
    if ((a > b) == up) { unsigned long long t = a; a = b; b = t; }
}
__device__ __forceinline__ void merge8(unsigned long long* k, bool up) {
    ce(k[0], k[4], up); ce(k[1], k[5], up); ce(k[2], k[6], up); ce(k[3], k[7], up);
    ce(k[0], k[2], up); ce(k[1], k[3], up); ce(k[4], k[6], up); ce(k[5], k[7], up);
    ce(k[0], k[1], up); ce(k[2], k[3], up); ce(k[4], k[5], up); ce(k[6], k[7], up);
}

// ---------------------------------------------------------------------------
// Fused kernel. grid = (8, 512), block = 256, 2 CTAs/SM (regs<=128, L1 92KB).
// ---------------------------------------------------------------------------
__global__ __launch_bounds__(256, 2) void fused_kernel(const float* __restrict__ x,
                                                       const float* __restrict__ trafo,
                                                       float* __restrict__ out) {
    extern __shared__ char smem[];
    __shared__ unsigned s_last;

    const int y = blockIdx.y;
    const int bid = blockIdx.x + (y << 3);
    const int tileRow = blockIdx.x * TILE_ROWS;
    const int t = threadIdx.x;
    const int wid = t >> 5;
    const int lid = t & 31;

    // ---- B-fragment table (bid 0; 512 items, 2 per thread) ----
    if (bid == 0) {
        #pragma unroll
        for (int half = 0; half < 2; half++) {
            int it = t + 256 * half;
            int ng = it >> 8;
            int kc = (it >> 5) & 7;
            int lane = it & 31;
            int n_base = ng * 32 + (lane >> 2);
            int k_base = kc * 16 + 2 * (lane & 3);
            uint32_t rh[8], rl[8];
            #pragma unroll
            for (int nt = 0; nt < 4; nt++)
                #pragma unroll
                for (int r = 0; r < 2; r++) {
                    int n = n_base + 8 * nt;
                    int k = k_base + 8 * r;
                    unsigned short h0, l0, h1, l1;
                    bf16_split(trafo[k * NDIM + n], h0, l0);
                    bf16_split(trafo[(k + 1) * NDIM + n], h1, l1);
                    rh[2 * nt + r] = (uint32_t)h0 | ((uint32_t)h1 << 16);
                    rl[2 * nt + r] = (uint32_t)l0 | ((uint32_t)l1 << 16);
                }
            uint4* dst = g_Bfrag + (ng * 8 + kc) * 128 + lane;
            dst[0]  = make_uint4(rh[0], rh[1], rh[2], rh[3]);
            dst[32] = make_uint4(rh[4], rh[5], rh[6], rh[7]);
            dst[64] = make_uint4(rl[0], rl[1], rl[2], rl[3]);
            dst[96] = make_uint4(rl[4], rl[5], rl[6], rl[7]);
        }
        __syncthreads();
        __threadfence();
        if (t == 0) st_release(&g_bflag, 1);
    }

    // ---- Sort batch `bid` (bid < 512): 256 threads x 8 keys ----
    if (bid < BATCH) {
        unsigned long long* keys = (unsigned long long*)smem;   // 16KB overlay
        const float* xb = x + (size_t)bid * GS * PARAM;

        unsigned long long key[8];
        #pragma unroll
        for (int i = 0; i < 8; i++) {
            int e = 8 * t + i;
            unsigned u = __float_as_uint(xb[(size_t)e * PARAM + (PARAM - 1)]);
            unsigned m = (u & 0x80000000u) ? ~u : (u | 0x80000000u);
            key[i] = ((unsigned long long)(~m) << 32) | (unsigned)e;
        }

        ce(key[0], key[1], true);  ce(key[2], key[3], false);
        ce(key[4], key[5], true);  ce(key[6], key[7], false);
        ce(key[0], key[2], true);  ce(key[1], key[3], true);
        ce(key[0], key[1], true);  ce(key[2], key[3], true);
        ce(key[4], key[6], false); ce(key[5], key[7], false);
        ce(key[4], key[5], false); ce(key[6], key[7], false);
        merge8(key, (t & 1) == 0);

        #pragma unroll
        for (int k = 16; k <= 256; k <<= 1) {
            bool up = ((t & (k >> 3)) == 0);
            #pragma unroll
            for (int j = k >> 1; j >= 8; j >>= 1) {
                int d = j >> 3;
                bool keepmin = (((t & d) == 0) == up);
                #pragma unroll
                for (int i = 0; i < 8; i++) {
                    unsigned long long p = __shfl_xor_sync(0xffffffffu, key[i], d);
                    key[i] = keepmin ? (key[i] < p ? key[i] : p) : (key[i] > p ? key[i] : p);
                }
            }
            merge8(key, up);
        }

        for (int k = 512; k <= GS; k <<= 1) {
            #pragma unroll
            for (int i = 0; i < 8; i++) keys[8 * t + i] = key[i];
            __syncthreads();
            for (int j = k >> 1; j >= 256; j >>= 1) {
                #pragma unroll
                for (int q0 = 0; q0 < 4; q0++) {
                    int q = t + 256 * q0;
                    int i = ((q & ~(j - 1)) << 1) | (q & (j - 1));
                    bool up2 = ((i & k) == 0);
                    unsigned long long a = keys[i];
                    unsigned long long c = keys[i | j];
                    if ((a > c) == up2) { keys[i] = c; keys[i | j] = a; }
                }
                __syncthreads();
            }
            #pragma unroll
            for (int i = 0; i < 8; i++) key[i] = keys[8 * t + i];
            bool up = ((t & (k >> 3)) == 0);
            #pragma unroll
            for (int j = 128; j >= 8; j >>= 1) {
                int d = j >> 3;
                bool keepmin = (((t & d) == 0) == up);
                #pragma unroll
                for (int i = 0; i < 8; i++) {
                    unsigned long long p = __shfl_xor_sync(0xffffffffu, key[i], d);
                    key[i] = keepmin ? (key[i] < p ? key[i] : p) : (key[i] > p ? key[i] : p);
                }
            }
            merge8(key, up);
        }

        #pragma unroll
        for (int i = 0; i < 8; i++)
            g_order[bid * GS + 8 * t + i] = (unsigned)(key[i] & 0xffffffffu);

        __syncthreads();
        __threadfence();
        if (t == 0) st_release(&g_flag[bid], 1);
    }

    // ---- Wait for this batch's order (sorter bid = y <= our bid) ----
    if (t == 0) {
        while (ld_acquire(&g_flag[y]) == 0) __nanosleep(64);
    }
    __syncthreads();

    // ---- Gather 256 x-rows -> bf16 hi/lo A tiles (idx prefetch) ----
    unsigned short* Ah = (unsigned short*)(smem + OFF_AH);
    unsigned short* Al = (unsigned short*)(smem + OFF_AL);
    {
        const float* xb = x + (size_t)y * GS * PARAM;
        const int lane16 = t & 15;
        const unsigned* ord = g_order + y * GS + 2 * tileRow;
        unsigned idx[16];
        #pragma unroll
        for (int pass = 0; pass < 16; pass++)
            idx[pass] = ord[pass * 16 + (t >> 4)];
        #pragma unroll
        for (int pass = 0; pass < 16; pass++) {
            int s = pass * 16 + (t >> 4);
            float4 v = ((const float4*)(xb + (size_t)idx[pass] * PARAM))[lane16];
            int r = s >> 1;
            int koff = (s & 1) * PARAM + lane16 * 4;
            unsigned short h[4], l[4];
            bf16_split(v.x, h[0], l[0]);
            bf16_split(v.y, h[1], l[1]);
            bf16_split(v.z, h[2], l[2]);
            bf16_split(v.w, h[3], l[3]);
            uint2 hp, lp;
            hp.x = (uint32_t)h[0] | ((uint32_t)h[1] << 16);
            hp.y = (uint32_t)h[2] | ((uint32_t)h[3] << 16);
            lp.x = (uint32_t)l[0] | ((uint32_t)l[1] << 16);
            lp.y = (uint32_t)l[2] | ((uint32_t)l[3] << 16);
            *(uint2*)(Ah + r * APITCH + koff) = hp;
            *(uint2*)(Al + r * APITCH + koff) = lp;
        }
    }

    if (t == 0) {
        while (ld_acquire(&g_bflag) == 0) __nanosleep(64);
    }
    __syncthreads();

    // ---- Mainloop: 8 warps, warp w -> rows (w&3)*32, cols (w>>2)*32.
    //      B fragments double-buffered across kc (regs budget 128). ----
    const int wm = (wid & 3) * 32;
    const int ng = wid >> 2;
    const uint32_t sb32 = smem_u32(smem);

    uint32_t a_addr = sb32 + OFF_AH +
        (((uint32_t)(wm + (lid & 15)) * APITCH + (uint32_t)((lid >> 4) * 8)) << 1);
    const uint32_t A_LO = OFF_AL - OFF_AH;
    const uint32_t A_MT = 16 * APITCH * 2;

    const uint4* Bf = g_Bfrag + ng * (8 * 128) + lid;

    float d[2][4][4];
    #pragma unroll
    for (int mt = 0; mt < 2; mt++)
        #pragma unroll
        for (int nt = 0; nt < 4; nt++)
            #pragma unroll
            for (int e = 0; e < 4; e++) d[mt][nt][e] = 0.f;

    uint4 f0 = __ldg(Bf);
    uint4 f1 = __ldg(Bf + 32);
    uint4 f2 = __ldg(Bf + 64);
    uint4 f3 = __ldg(Bf + 96);

    #pragma unroll
    for (int kc = 0; kc < 8; kc++) {
        // Prefetch next kc's B fragments before this kc's math.
        uint4 n0, n1, n2, n3;
        if (kc < 7) {
            n0 = __ldg(Bf + (kc + 1) * 128);
            n1 = __ldg(Bf + (kc + 1) * 128 + 32);
            n2 = __ldg(Bf + (kc + 1) * 128 + 64);
            n3 = __ldg(Bf + (kc + 1) * 128 + 96);
        }
        const uint32_t ko = kc * 32;
        uint32_t ah[2][4], al[2][4];
        LDM4(ah[0], a_addr + ko);
        LDM4(ah[1], a_addr + A_MT + ko);
        LDM4(al[0], a_addr + A_LO + ko);
        LDM4(al[1], a_addr + A_LO + A_MT + ko);

        #pragma unroll
        for (int mt = 0; mt < 2; mt++) {
            MMA(d[mt][0], ah[mt], f0.x, f0.y);
            MMA(d[mt][1], ah[mt], f0.z, f0.w);
            MMA(d[mt][2], ah[mt], f1.x, f1.y);
            MMA(d[mt][3], ah[mt], f1.z, f1.w);
            MMA(d[mt][0], ah[mt], f2.x, f2.y);
            MMA(d[mt][1], ah[mt], f2.z, f2.w);
            MMA(d[mt][2], ah[mt], f3.x, f3.y);
            MMA(d[mt][3], ah[mt], f3.z, f3.w);
            MMA(d[mt][0], al[mt], f0.x, f0.y);
            MMA(d[mt][1], al[mt], f0.z, f0.w);
            MMA(d[mt][2], al[mt], f1.x, f1.y);
            MMA(d[mt][3], al[mt], f1.z, f1.w);
        }
        if (kc < 7) { f0 = n0; f1 = n1; f2 = n2; f3 = n3; }
    }

    float* baseo = out + ((size_t)y * OGS + tileRow) * NDIM;
    const int wn = ng * 32;
    #pragma unroll
    for (int mt = 0; mt < 2; mt++)
        #pragma unroll
        for (int nt = 0; nt < 4; nt++) {
            int r = wm + 16 * mt + (lid >> 2);
            int c = wn + 8 * nt + 2 * (lid & 3);
            *(float2*)(baseo + (size_t)r * NDIM + c) =
                make_float2(d[mt][nt][0], d[mt][nt][1]);
            *(float2*)(baseo + (size_t)(r + 8) * NDIM + c) =
                make_float2(d[mt][nt][2], d[mt][nt][3]);
        }

    // ---- Flag reset by the last CTA to finish ----
    __syncthreads();
    if (t == 0) {
        unsigned done = atomicAdd(&g_done, 1u);
        s_last = (done == (unsigned)(8 * BATCH - 1)) ? 1u : 0u;
    }
    __syncthreads();
    if (s_last) {
        for (int i = t; i < BATCH; i += 256) g_flag[i] = 0;
        if (t == 0) { g_bflag = 0; g_done = 0u; }
    }
}

extern "C" void kernel_launch(void* const* d_in, const int* in_sizes, int n_in,
                              void* d_out, int out_size) {
    const float* x     = (const float*)d_in[0];
    const float* trafo = (const float*)d_in[1];
    float* out         = (float*)d_out;

    cudaFuncSetAttribute(fused_kernel, cudaFuncAttributeMaxDynamicSharedMemorySize,
                         SMEM_BYTES);
    dim3 grid(OGS / TILE_ROWS, BATCH);
    fused_kernel<<<grid, 256, SMEM_BYTES>>>(x, trafo, out);
}